// round 1
// baseline (speedup 1.0000x reference)
#include <cuda_runtime.h>
#include <math.h>

#define B_ 4
#define S_ 2048
#define E_ 1024
#define H_ 16
#define D_ 64
#define BS_ (B_*S_)

// Scratch (device globals — no allocations allowed)
__device__ float g_Q[B_*H_*S_*D_];
__device__ float g_K[B_*H_*S_*D_];
__device__ float g_V[B_*H_*S_*D_];
__device__ float g_ctx[BS_*H_*D_];   // [B,S,H,D] == concat layout

// ---------------------------------------------------------------------------
// Kernel 1: fused QKV projection.
// C[128x64] = x_tile[128xE] * W_h[Ex64] + bias, per (m-tile, head, {q,k,v}).
// grid (BS/128, H, 3), block 256 (tx 0..15 over N, ty 0..15 over M; 8x4/thread)
// ---------------------------------------------------------------------------
__global__ __launch_bounds__(256) void qkv_kernel(
    const float* __restrict__ x,
    const float* __restrict__ Wq, const float* __restrict__ Wk, const float* __restrict__ Wv,
    const float* __restrict__ bq, const float* __restrict__ bk, const float* __restrict__ bv)
{
    __shared__ float As[128][36];   // pad 36: float4-aligned rows, conflict-free
    __shared__ float Ws[32][64];

    const int m0 = blockIdx.x * 128;
    const int h  = blockIdx.y;
    const int w  = blockIdx.z;
    const float* Wsel = (w == 0 ? Wq : (w == 1 ? Wk : Wv)) + (size_t)h * E_ * D_;
    const float* bsel = (w == 0 ? bq : (w == 1 ? bk : bv)) + h * D_;
    float* out = (w == 0 ? g_Q : (w == 1 ? g_K : g_V));

    const int tid = threadIdx.x;
    const int tx = tid & 15;
    const int ty = tid >> 4;

    float acc[8][4];
    #pragma unroll
    for (int i = 0; i < 8; i++)
        #pragma unroll
        for (int j = 0; j < 4; j++) acc[i][j] = 0.f;

    for (int k0 = 0; k0 < E_; k0 += 32) {
        // load x tile 128x32 (float4, coalesced)
        #pragma unroll
        for (int i = 0; i < 4; i++) {
            int lin = tid + i * 256;       // float4 units (1024 total)
            int row = lin >> 3;            // 8 float4 per row
            int c4  = lin & 7;
            float4 v = *(const float4*)(x + (size_t)(m0 + row) * E_ + k0 + c4 * 4);
            *(float4*)&As[row][c4 * 4] = v;
        }
        // load W tile 32x64
        #pragma unroll
        for (int i = 0; i < 2; i++) {
            int lin = tid + i * 256;       // float4 units (512 total)
            int row = lin >> 4;            // 16 float4 per row
            int c4  = lin & 15;
            *(float4*)&Ws[row][c4 * 4] =
                *(const float4*)(Wsel + (size_t)(k0 + row) * D_ + c4 * 4);
        }
        __syncthreads();

        #pragma unroll
        for (int kk = 0; kk < 32; kk++) {
            float a[8];
            #pragma unroll
            for (int i = 0; i < 8; i++) a[i] = As[ty * 8 + i][kk];
            float4 b4 = *(float4*)&Ws[kk][tx * 4];
            float bb[4] = {b4.x, b4.y, b4.z, b4.w};
            #pragma unroll
            for (int i = 0; i < 8; i++)
                #pragma unroll
                for (int j = 0; j < 4; j++)
                    acc[i][j] += a[i] * bb[j];
        }
        __syncthreads();
    }

    // store to [B,H,S,D] with bias
    const int b  = m0 / S_;
    const int s0 = m0 % S_;
    float4 bias = *(const float4*)(bsel + tx * 4);
    #pragma unroll
    for (int i = 0; i < 8; i++) {
        int s = s0 + ty * 8 + i;
        float4 v;
        v.x = acc[i][0] + bias.x;
        v.y = acc[i][1] + bias.y;
        v.z = acc[i][2] + bias.z;
        v.w = acc[i][3] + bias.w;
        *(float4*)(out + (((size_t)b * H_ + h) * S_ + s) * D_ + tx * 4) = v;
    }
}

// ---------------------------------------------------------------------------
// Kernel 2: causal flash attention. One block = 64 queries of one (b,h).
// grid (S/64, H, B), block 256. Online softmax, 4x4 micro-tiles.
// Writes ctx directly in [B,S,H,D] (concat for free).
// ---------------------------------------------------------------------------
#define PADQ 65
#define FLASH_SMEM (4 * 64 * PADQ * 4)

__global__ __launch_bounds__(256) void flash_kernel()
{
    extern __shared__ float sm[];
    float* Qs = sm;                 // [64][65]
    float* Ks = Qs + 64 * PADQ;
    float* Vs = Ks + 64 * PADQ;
    float* Ps = Vs + 64 * PADQ;

    const int iq = blockIdx.x;
    const int h  = blockIdx.y;
    const int b  = blockIdx.z;
    const int q0 = iq * 64;

    const size_t head_base = ((size_t)b * H_ + h) * S_ * D_;
    const float* Qg = g_Q + head_base;
    const float* Kg = g_K + head_base;
    const float* Vg = g_V + head_base;

    const int tid = threadIdx.x;
    const int tx = tid & 15;       // key/d cols: 4 each
    const int ty = tid >> 4;       // query rows: 4 each

    // load Q tile pre-scaled by 1/sqrt(D)
    #pragma unroll
    for (int i = 0; i < 4; i++) {
        int lin = tid + i * 256;   // float4 units (1024)
        int row = lin >> 4;
        int c4  = lin & 15;
        float4 v = *(const float4*)(Qg + (size_t)(q0 + row) * D_ + c4 * 4);
        Qs[row * PADQ + c4 * 4 + 0] = v.x * 0.125f;
        Qs[row * PADQ + c4 * 4 + 1] = v.y * 0.125f;
        Qs[row * PADQ + c4 * 4 + 2] = v.z * 0.125f;
        Qs[row * PADQ + c4 * 4 + 3] = v.w * 0.125f;
    }

    float m_i[4], l_i[4], acc[4][4];
    #pragma unroll
    for (int i = 0; i < 4; i++) {
        m_i[i] = -1e30f;
        l_i[i] = 0.f;
        #pragma unroll
        for (int j = 0; j < 4; j++) acc[i][j] = 0.f;
    }
    __syncthreads();

    for (int jt = 0; jt <= iq; jt++) {
        const int k0 = jt * 64;
        // load K and V tiles
        #pragma unroll
        for (int i = 0; i < 4; i++) {
            int lin = tid + i * 256;
            int row = lin >> 4;
            int c4  = lin & 15;
            float4 kv = *(const float4*)(Kg + (size_t)(k0 + row) * D_ + c4 * 4);
            Ks[row * PADQ + c4 * 4 + 0] = kv.x;
            Ks[row * PADQ + c4 * 4 + 1] = kv.y;
            Ks[row * PADQ + c4 * 4 + 2] = kv.z;
            Ks[row * PADQ + c4 * 4 + 3] = kv.w;
            float4 vv = *(const float4*)(Vg + (size_t)(k0 + row) * D_ + c4 * 4);
            Vs[row * PADQ + c4 * 4 + 0] = vv.x;
            Vs[row * PADQ + c4 * 4 + 1] = vv.y;
            Vs[row * PADQ + c4 * 4 + 2] = vv.z;
            Vs[row * PADQ + c4 * 4 + 3] = vv.w;
        }
        __syncthreads();

        // S = (Q/sqrt(D)) K^T
        float s[4][4];
        #pragma unroll
        for (int i = 0; i < 4; i++)
            #pragma unroll
            for (int j = 0; j < 4; j++) s[i][j] = 0.f;

        #pragma unroll 16
        for (int dd = 0; dd < 64; dd++) {
            float a[4], bb[4];
            #pragma unroll
            for (int i = 0; i < 4; i++) a[i]  = Qs[(ty * 4 + i) * PADQ + dd];
            #pragma unroll
            for (int j = 0; j < 4; j++) bb[j] = Ks[(tx * 4 + j) * PADQ + dd];
            #pragma unroll
            for (int i = 0; i < 4; i++)
                #pragma unroll
                for (int j = 0; j < 4; j++)
                    s[i][j] += a[i] * bb[j];
        }

        // causal mask only on the diagonal tile
        if (jt == iq) {
            #pragma unroll
            for (int i = 0; i < 4; i++)
                #pragma unroll
                for (int j = 0; j < 4; j++)
                    if (k0 + tx * 4 + j > q0 + ty * 4 + i) s[i][j] = -1e30f;
        }

        // online softmax (row stats reduced over tx lanes via shfl)
        #pragma unroll
        for (int i = 0; i < 4; i++) {
            float rm = fmaxf(fmaxf(s[i][0], s[i][1]), fmaxf(s[i][2], s[i][3]));
            rm = fmaxf(rm, __shfl_xor_sync(0xffffffffu, rm, 1));
            rm = fmaxf(rm, __shfl_xor_sync(0xffffffffu, rm, 2));
            rm = fmaxf(rm, __shfl_xor_sync(0xffffffffu, rm, 4));
            rm = fmaxf(rm, __shfl_xor_sync(0xffffffffu, rm, 8));
            float mn = fmaxf(m_i[i], rm);
            float corr = __expf(m_i[i] - mn);
            m_i[i] = mn;
            float rs = 0.f;
            #pragma unroll
            for (int j = 0; j < 4; j++) {
                float p = __expf(s[i][j] - mn);
                s[i][j] = p;
                rs += p;
            }
            rs += __shfl_xor_sync(0xffffffffu, rs, 1);
            rs += __shfl_xor_sync(0xffffffffu, rs, 2);
            rs += __shfl_xor_sync(0xffffffffu, rs, 4);
            rs += __shfl_xor_sync(0xffffffffu, rs, 8);
            l_i[i] = l_i[i] * corr + rs;
            #pragma unroll
            for (int j = 0; j < 4; j++) acc[i][j] *= corr;
        }

        // materialize P
        #pragma unroll
        for (int i = 0; i < 4; i++)
            #pragma unroll
            for (int j = 0; j < 4; j++)
                Ps[(ty * 4 + i) * PADQ + tx * 4 + j] = s[i][j];
        __syncthreads();

        // O += P V
        #pragma unroll 16
        for (int kk = 0; kk < 64; kk++) {
            float a[4], bb[4];
            #pragma unroll
            for (int i = 0; i < 4; i++) a[i]  = Ps[(ty * 4 + i) * PADQ + kk];
            #pragma unroll
            for (int j = 0; j < 4; j++) bb[j] = Vs[kk * PADQ + tx * 4 + j];
            #pragma unroll
            for (int i = 0; i < 4; i++)
                #pragma unroll
                for (int j = 0; j < 4; j++)
                    acc[i][j] += a[i] * bb[j];
        }
        __syncthreads();
    }

    // epilogue: normalize + write ctx in [B,S,H,D]
    #pragma unroll
    for (int i = 0; i < 4; i++) {
        float inv = 1.0f / l_i[i];
        int q = q0 + ty * 4 + i;
        float4 v;
        v.x = acc[i][0] * inv;
        v.y = acc[i][1] * inv;
        v.z = acc[i][2] * inv;
        v.w = acc[i][3] * inv;
        *(float4*)(g_ctx + (((size_t)b * S_ + q) * H_ + h) * D_ + tx * 4) = v;
    }
}

// ---------------------------------------------------------------------------
// Kernel 3: output projection. out[BS,E] = ctx[BS,1024] * Wo[1024,E] + bo
// grid (BS/128, E/64), block 256, same tiling as kernel 1.
// ---------------------------------------------------------------------------
__global__ __launch_bounds__(256) void oproj_kernel(
    const float* __restrict__ Wo, const float* __restrict__ bo,
    float* __restrict__ out)
{
    __shared__ float As[128][36];
    __shared__ float Ws[32][64];

    const int m0 = blockIdx.x * 128;
    const int n0 = blockIdx.y * 64;
    const int tid = threadIdx.x;
    const int tx = tid & 15;
    const int ty = tid >> 4;

    float acc[8][4];
    #pragma unroll
    for (int i = 0; i < 8; i++)
        #pragma unroll
        for (int j = 0; j < 4; j++) acc[i][j] = 0.f;

    const int KD = H_ * D_;  // 1024
    for (int k0 = 0; k0 < KD; k0 += 32) {
        #pragma unroll
        for (int i = 0; i < 4; i++) {
            int lin = tid + i * 256;
            int row = lin >> 3;
            int c4  = lin & 7;
            *(float4*)&As[row][c4 * 4] =
                *(const float4*)(g_ctx + (size_t)(m0 + row) * KD + k0 + c4 * 4);
        }
        #pragma unroll
        for (int i = 0; i < 2; i++) {
            int lin = tid + i * 256;
            int row = lin >> 4;
            int c4  = lin & 15;
            *(float4*)&Ws[row][c4 * 4] =
                *(const float4*)(Wo + (size_t)(k0 + row) * E_ + n0 + c4 * 4);
        }
        __syncthreads();

        #pragma unroll
        for (int kk = 0; kk < 32; kk++) {
            float a[8];
            #pragma unroll
            for (int i = 0; i < 8; i++) a[i] = As[ty * 8 + i][kk];
            float4 b4 = *(float4*)&Ws[kk][tx * 4];
            float bb[4] = {b4.x, b4.y, b4.z, b4.w};
            #pragma unroll
            for (int i = 0; i < 8; i++)
                #pragma unroll
                for (int j = 0; j < 4; j++)
                    acc[i][j] += a[i] * bb[j];
        }
        __syncthreads();
    }

    float4 bias = *(const float4*)(bo + n0 + tx * 4);
    #pragma unroll
    for (int i = 0; i < 8; i++) {
        int m = m0 + ty * 8 + i;
        float4 v;
        v.x = acc[i][0] + bias.x;
        v.y = acc[i][1] + bias.y;
        v.z = acc[i][2] + bias.z;
        v.w = acc[i][3] + bias.w;
        *(float4*)(out + (size_t)m * E_ + n0 + tx * 4) = v;
    }
}

// ---------------------------------------------------------------------------
extern "C" void kernel_launch(void* const* d_in, const int* in_sizes, int n_in,
                              void* d_out, int out_size)
{
    const float* x  = (const float*)d_in[0];
    const float* Wq = (const float*)d_in[1];
    const float* Wk = (const float*)d_in[2];
    const float* Wv = (const float*)d_in[3];
    const float* bq = (const float*)d_in[4];
    const float* bk = (const float*)d_in[5];
    const float* bv = (const float*)d_in[6];
    const float* Wo = (const float*)d_in[7];
    const float* bo = (const float*)d_in[8];
    float* out = (float*)d_out;

    // >48KB dynamic smem opt-in (idempotent, not a stream op — capture-safe)
    cudaFuncSetAttribute(flash_kernel,
                         cudaFuncAttributeMaxDynamicSharedMemorySize, FLASH_SMEM);

    qkv_kernel<<<dim3(BS_ / 128, H_, 3), 256>>>(x, Wq, Wk, Wv, bq, bk, bv);
    flash_kernel<<<dim3(S_ / 64, H_, B_), 256, FLASH_SMEM>>>();
    oproj_kernel<<<dim3(BS_ / 128, E_ / 64), 256>>>(Wo, bo, out);
}

// round 2
// speedup vs baseline: 2.3517x; 2.3517x over previous
#include <cuda_runtime.h>
#include <math.h>

#define B_ 4
#define S_ 2048
#define E_ 1024
#define H_ 16
#define D_ 64
#define BS_ (B_*S_)

// Scratch (device globals — no allocations allowed)
__device__ float g_Q[B_*H_*S_*D_];
__device__ float g_K[B_*H_*S_*D_];
__device__ float g_V[B_*H_*S_*D_];
__device__ float g_ctx[BS_*H_*D_];   // [B,S,H,D] == concat layout

// ---------------------------------------------------------------------------
// helpers: tf32 convert (rna: unbiased) + m16n8k8 tf32 mma
// ---------------------------------------------------------------------------
__device__ __forceinline__ unsigned f2tf(float f) {
    unsigned u;
    asm("cvt.rna.tf32.f32 %0, %1;" : "=r"(u) : "f"(f));
    return u;
}
__device__ __forceinline__ float f2tff(float f) { return __uint_as_float(f2tf(f)); }

__device__ __forceinline__ void mma8(float* c, const unsigned* a, const unsigned* b) {
    asm volatile(
        "mma.sync.aligned.m16n8k8.row.col.f32.tf32.tf32.f32 "
        "{%0,%1,%2,%3}, {%4,%5,%6,%7}, {%8,%9}, {%0,%1,%2,%3};\n"
        : "+f"(c[0]), "+f"(c[1]), "+f"(c[2]), "+f"(c[3])
        : "r"(a[0]), "r"(a[1]), "r"(a[2]), "r"(a[3]), "r"(b[0]), "r"(b[1]));
}

// ---------------------------------------------------------------------------
// Kernel 1: fused QKV projection, tf32 mma.
// Block tile 256(M) x 128(N = two (w,h) 64-col outputs), K-tile 16.
// 512 threads = 16 warps as 8(M) x 2(N); warp tile 32x64.
// grid (BS/256, 24)
// ---------------------------------------------------------------------------
__global__ __launch_bounds__(512) void qkv_kernel(
    const float* __restrict__ x,
    const float* __restrict__ Wq, const float* __restrict__ Wk, const float* __restrict__ Wv,
    const float* __restrict__ bq, const float* __restrict__ bk, const float* __restrict__ bv)
{
    __shared__ float As[256][20];    // stride 20  (≡4 mod 32: A-frag conflict-free)
    __shared__ float Bs[16][136];    // stride 136 (≡8 mod 32: B-frag conflict-free)

    const int tid  = threadIdx.x;
    const int m0   = blockIdx.x * 256;
    const int p0   = blockIdx.y * 2;     // p = w*16 + h, two per block
    const int lane = tid & 31;
    const int wid  = tid >> 5;
    const int wm   = wid >> 1;           // 0..7
    const int wn   = wid & 1;            // 0..1
    const int g    = lane >> 2;
    const int t    = lane & 3;

    // per-thread B gmem source (fixed column across K loop)
    const int brow = tid >> 5;           // 0..15
    const int bcol = (tid & 31) * 4;     // 0..124
    const int pb   = p0 + (bcol >> 6);
    const int wB   = pb >> 4, hB = pb & 15;
    const float* bsrc = ((wB == 0) ? Wq : (wB == 1) ? Wk : Wv)
                        + (size_t)hB * E_ * D_ + (bcol & 63);

    float c[2][8][4];
    #pragma unroll
    for (int mi = 0; mi < 2; mi++)
        #pragma unroll
        for (int f = 0; f < 8; f++)
            #pragma unroll
            for (int r = 0; r < 4; r++) c[mi][f][r] = 0.f;

    for (int k0 = 0; k0 < E_; k0 += 16) {
        // load A tile 256x16
        #pragma unroll
        for (int i = 0; i < 2; i++) {
            int lin = tid + i * 512;           // float4 units (1024)
            int row = lin >> 2, c4 = lin & 3;
            float4 v = *(const float4*)(x + (size_t)(m0 + row) * E_ + k0 + c4 * 4);
            float4 w;
            w.x = f2tff(v.x); w.y = f2tff(v.y); w.z = f2tff(v.z); w.w = f2tff(v.w);
            *(float4*)&As[row][c4 * 4] = w;
        }
        // load B tile 16x128
        {
            float4 v = *(const float4*)(bsrc + (size_t)(k0 + brow) * D_);
            float4 w;
            w.x = f2tff(v.x); w.y = f2tff(v.y); w.z = f2tff(v.z); w.w = f2tff(v.w);
            *(float4*)&Bs[brow][bcol] = w;
        }
        __syncthreads();

        #pragma unroll
        for (int ks = 0; ks < 2; ks++) {
            const int k8 = ks * 8;
            unsigned a[2][4];
            #pragma unroll
            for (int mi = 0; mi < 2; mi++) {
                int r = wm * 32 + mi * 16 + g;
                a[mi][0] = __float_as_uint(As[r][k8 + t]);
                a[mi][1] = __float_as_uint(As[r + 8][k8 + t]);
                a[mi][2] = __float_as_uint(As[r][k8 + t + 4]);
                a[mi][3] = __float_as_uint(As[r + 8][k8 + t + 4]);
            }
            #pragma unroll
            for (int f = 0; f < 8; f++) {
                unsigned b[2];
                const int nc = wn * 64 + f * 8 + g;
                b[0] = __float_as_uint(Bs[k8 + t][nc]);
                b[1] = __float_as_uint(Bs[k8 + t + 4][nc]);
                mma8(c[0][f], a[0], b);
                mma8(c[1][f], a[1], b);
            }
        }
        __syncthreads();
    }

    // epilogue: bias + store to [B,H,S,D]
    const int p = p0 + wn;
    const int w = p >> 4, h = p & 15;
    float* outb = (w == 0) ? g_Q : (w == 1) ? g_K : g_V;
    const float* bb = ((w == 0) ? bq : (w == 1) ? bk : bv) + h * D_;

    #pragma unroll
    for (int mi = 0; mi < 2; mi++) {
        const int r0 = m0 + wm * 32 + mi * 16 + g;
        #pragma unroll
        for (int f = 0; f < 8; f++) {
            const int col = f * 8 + t * 2;
            const float b0v = bb[col], b1v = bb[col + 1];
            {
                int gr = r0;
                float2 v; v.x = c[mi][f][0] + b0v; v.y = c[mi][f][1] + b1v;
                *(float2*)(outb + (((size_t)(gr >> 11) * H_ + h) * S_ + (gr & 2047)) * D_ + col) = v;
            }
            {
                int gr = r0 + 8;
                float2 v; v.x = c[mi][f][2] + b0v; v.y = c[mi][f][3] + b1v;
                *(float2*)(outb + (((size_t)(gr >> 11) * H_ + h) * S_ + (gr & 2047)) * D_ + col) = v;
            }
        }
    }
}

// ---------------------------------------------------------------------------
// Kernel 2: causal flash attention with tf32 mma.
// Block = 128 queries of one (b,h), Bkv=64, 256 threads / 8 warps.
// Warp w owns query rows 16w..16w+15 (whole softmax row inside one quad).
// ---------------------------------------------------------------------------
#define QS_OFF 0
#define KS_OFF 8704              /* 128*68 */
#define VS_OFF 13056             /* + 64*68 */
#define PS_OFF 17664             /* + 64*72 */
#define FLASH_SMEM ((17664 + 8704) * 4)

__global__ __launch_bounds__(256) void flash_kernel()
{
    extern __shared__ float sm[];
    float* Qs = sm + QS_OFF;     // [128][68]  A-role
    float* Ks = sm + KS_OFF;     // [64][68]   read as B[d][key]=Ks[key][d]
    float* Vs = sm + VS_OFF;     // [64][72]   read as B[key][d]=Vs[key][d]
    float* Ps = sm + PS_OFF;     // [128][68]  A-role

    const int iq = blockIdx.x;
    const int h  = blockIdx.y;
    const int b  = blockIdx.z;
    const int q0 = iq * 128;

    const size_t head_base = ((size_t)b * H_ + h) * S_ * D_;
    const float* Qg = g_Q + head_base;
    const float* Kg = g_K + head_base;
    const float* Vg = g_V + head_base;

    const int tid  = threadIdx.x;
    const int lane = tid & 31;
    const int wid  = tid >> 5;       // 0..7
    const int g    = lane >> 2;
    const int t    = lane & 3;
    const int qrow = wid * 16 + g;   // this thread's base query row (and +8)

    // load Q tile (scaled by 1/sqrt(D), tf32-rounded)
    #pragma unroll
    for (int i = 0; i < 8; i++) {
        int lin = tid + i * 256;     // float4 units (2048)
        int row = lin >> 4, c4 = lin & 15;
        float4 v = *(const float4*)(Qg + (size_t)(q0 + row) * D_ + c4 * 4);
        float4 w;
        w.x = f2tff(v.x * 0.125f); w.y = f2tff(v.y * 0.125f);
        w.z = f2tff(v.z * 0.125f); w.w = f2tff(v.w * 0.125f);
        *(float4*)&Qs[row * 68 + c4 * 4] = w;
    }

    float cO[8][4];
    #pragma unroll
    for (int f = 0; f < 8; f++)
        #pragma unroll
        for (int r = 0; r < 4; r++) cO[f][r] = 0.f;
    float m0_ = -1e30f, m1_ = -1e30f, l0_ = 0.f, l1_ = 0.f;

    const int jtmax = 2 * iq + 1;
    for (int jt = 0; jt <= jtmax; jt++) {
        const int k0 = jt * 64;
        // load K,V tiles (64x64 each)
        #pragma unroll
        for (int i = 0; i < 4; i++) {
            int lin = tid + i * 256;
            int row = lin >> 4, c4 = lin & 15;
            float4 kv = *(const float4*)(Kg + (size_t)(k0 + row) * D_ + c4 * 4);
            float4 wk2;
            wk2.x = f2tff(kv.x); wk2.y = f2tff(kv.y); wk2.z = f2tff(kv.z); wk2.w = f2tff(kv.w);
            *(float4*)&Ks[row * 68 + c4 * 4] = wk2;
            float4 vv = *(const float4*)(Vg + (size_t)(k0 + row) * D_ + c4 * 4);
            float4 wv2;
            wv2.x = f2tff(vv.x); wv2.y = f2tff(vv.y); wv2.z = f2tff(vv.z); wv2.w = f2tff(vv.w);
            *(float4*)&Vs[row * 72 + c4 * 4] = wv2;
        }
        __syncthreads();

        // S = Q K^T : warp tile 16x64, 8 n-frags
        float cS[8][4];
        #pragma unroll
        for (int f = 0; f < 8; f++)
            #pragma unroll
            for (int r = 0; r < 4; r++) cS[f][r] = 0.f;

        #pragma unroll
        for (int kk = 0; kk < 8; kk++) {
            const int d8 = kk * 8;
            unsigned a[4];
            a[0] = __float_as_uint(Qs[qrow * 68 + d8 + t]);
            a[1] = __float_as_uint(Qs[(qrow + 8) * 68 + d8 + t]);
            a[2] = __float_as_uint(Qs[qrow * 68 + d8 + t + 4]);
            a[3] = __float_as_uint(Qs[(qrow + 8) * 68 + d8 + t + 4]);
            #pragma unroll
            for (int f = 0; f < 8; f++) {
                unsigned bfr[2];
                // B[d][key]: logical row d=d8+t(+4), col key=f*8+g -> Ks[key][d]
                bfr[0] = __float_as_uint(Ks[(f * 8 + g) * 68 + d8 + t]);
                bfr[1] = __float_as_uint(Ks[(f * 8 + g) * 68 + d8 + t + 4]);
                mma8(cS[f], a, bfr);
            }
        }

        // causal mask (only the two diagonal-crossing tiles)
        if (jt >= 2 * iq) {
            const int r0 = q0 + qrow, r1 = r0 + 8;
            #pragma unroll
            for (int f = 0; f < 8; f++) {
                const int col = k0 + f * 8 + t * 2;
                if (col     > r0) cS[f][0] = -1e30f;
                if (col + 1 > r0) cS[f][1] = -1e30f;
                if (col     > r1) cS[f][2] = -1e30f;
                if (col + 1 > r1) cS[f][3] = -1e30f;
            }
        }

        // online softmax: rows qrow (regs 0,1) and qrow+8 (regs 2,3)
        float rm0 = -1e30f, rm1 = -1e30f;
        #pragma unroll
        for (int f = 0; f < 8; f++) {
            rm0 = fmaxf(rm0, fmaxf(cS[f][0], cS[f][1]));
            rm1 = fmaxf(rm1, fmaxf(cS[f][2], cS[f][3]));
        }
        rm0 = fmaxf(rm0, __shfl_xor_sync(0xffffffffu, rm0, 1));
        rm0 = fmaxf(rm0, __shfl_xor_sync(0xffffffffu, rm0, 2));
        rm1 = fmaxf(rm1, __shfl_xor_sync(0xffffffffu, rm1, 1));
        rm1 = fmaxf(rm1, __shfl_xor_sync(0xffffffffu, rm1, 2));

        const float nm0 = fmaxf(m0_, rm0);
        const float nm1 = fmaxf(m1_, rm1);
        const float corr0 = __expf(m0_ - nm0);
        const float corr1 = __expf(m1_ - nm1);
        m0_ = nm0; m1_ = nm1;

        float rs0 = 0.f, rs1 = 0.f;
        #pragma unroll
        for (int f = 0; f < 8; f++) {
            float p0v = __expf(cS[f][0] - nm0);
            float p1v = __expf(cS[f][1] - nm0);
            float p2v = __expf(cS[f][2] - nm1);
            float p3v = __expf(cS[f][3] - nm1);
            rs0 += p0v + p1v;
            rs1 += p2v + p3v;
            // materialize P (tf32) — warp-private rows
            float2 v0; v0.x = f2tff(p0v); v0.y = f2tff(p1v);
            *(float2*)&Ps[qrow * 68 + f * 8 + t * 2] = v0;
            float2 v1; v1.x = f2tff(p2v); v1.y = f2tff(p3v);
            *(float2*)&Ps[(qrow + 8) * 68 + f * 8 + t * 2] = v1;
        }
        rs0 += __shfl_xor_sync(0xffffffffu, rs0, 1);
        rs0 += __shfl_xor_sync(0xffffffffu, rs0, 2);
        rs1 += __shfl_xor_sync(0xffffffffu, rs1, 1);
        rs1 += __shfl_xor_sync(0xffffffffu, rs1, 2);
        l0_ = l0_ * corr0 + rs0;
        l1_ = l1_ * corr1 + rs1;
        #pragma unroll
        for (int f = 0; f < 8; f++) {
            cO[f][0] *= corr0; cO[f][1] *= corr0;
            cO[f][2] *= corr1; cO[f][3] *= corr1;
        }
        __syncwarp();

        // O += P V : A = Ps (warp-private), B[key][d] = Vs[key][d]
        #pragma unroll
        for (int kk = 0; kk < 8; kk++) {
            const int s8 = kk * 8;
            unsigned a[4];
            a[0] = __float_as_uint(Ps[qrow * 68 + s8 + t]);
            a[1] = __float_as_uint(Ps[(qrow + 8) * 68 + s8 + t]);
            a[2] = __float_as_uint(Ps[qrow * 68 + s8 + t + 4]);
            a[3] = __float_as_uint(Ps[(qrow + 8) * 68 + s8 + t + 4]);
            #pragma unroll
            for (int f = 0; f < 8; f++) {
                unsigned bfr[2];
                bfr[0] = __float_as_uint(Vs[(s8 + t) * 72 + f * 8 + g]);
                bfr[1] = __float_as_uint(Vs[(s8 + t + 4) * 72 + f * 8 + g]);
                mma8(cO[f], a, bfr);
            }
        }
        __syncthreads();   // before next tile overwrites Ks/Vs
    }

    // epilogue: normalize, tf32-round (oproj A operand), write ctx [B,S,H,D]
    const float inv0 = 1.0f / l0_;
    const float inv1 = 1.0f / l1_;
    const int q_a = q0 + qrow, q_b = q_a + 8;
    #pragma unroll
    for (int f = 0; f < 8; f++) {
        const int col = f * 8 + t * 2;
        float2 v0; v0.x = f2tff(cO[f][0] * inv0); v0.y = f2tff(cO[f][1] * inv0);
        *(float2*)(g_ctx + (((size_t)b * S_ + q_a) * H_ + h) * D_ + col) = v0;
        float2 v1; v1.x = f2tff(cO[f][2] * inv1); v1.y = f2tff(cO[f][3] * inv1);
        *(float2*)(g_ctx + (((size_t)b * S_ + q_b) * H_ + h) * D_ + col) = v1;
    }
}

// ---------------------------------------------------------------------------
// Kernel 3: output projection, tf32 mma. out = ctx[8192x1024] * Wo + bo
// Block tile 256x128, K-tile 16, 512 threads. grid (32, 8)
// ---------------------------------------------------------------------------
__global__ __launch_bounds__(512) void oproj_kernel(
    const float* __restrict__ Wo, const float* __restrict__ bo,
    float* __restrict__ out)
{
    __shared__ float As[256][20];
    __shared__ float Bs[16][136];

    const int tid  = threadIdx.x;
    const int m0   = blockIdx.x * 256;
    const int n0   = blockIdx.y * 128;
    const int lane = tid & 31;
    const int wid  = tid >> 5;
    const int wm   = wid >> 1;
    const int wn   = wid & 1;
    const int g    = lane >> 2;
    const int t    = lane & 3;

    const int brow = tid >> 5;
    const int bcol = (tid & 31) * 4;

    float c[2][8][4];
    #pragma unroll
    for (int mi = 0; mi < 2; mi++)
        #pragma unroll
        for (int f = 0; f < 8; f++)
            #pragma unroll
            for (int r = 0; r < 4; r++) c[mi][f][r] = 0.f;

    const int KD = H_ * D_;
    for (int k0 = 0; k0 < KD; k0 += 16) {
        #pragma unroll
        for (int i = 0; i < 2; i++) {
            int lin = tid + i * 512;
            int row = lin >> 2, c4 = lin & 3;
            // ctx already tf32-rounded by flash epilogue
            *(float4*)&As[row][c4 * 4] =
                *(const float4*)(g_ctx + (size_t)(m0 + row) * KD + k0 + c4 * 4);
        }
        {
            float4 v = *(const float4*)(Wo + (size_t)(k0 + brow) * E_ + n0 + bcol);
            float4 w;
            w.x = f2tff(v.x); w.y = f2tff(v.y); w.z = f2tff(v.z); w.w = f2tff(v.w);
            *(float4*)&Bs[brow][bcol] = w;
        }
        __syncthreads();

        #pragma unroll
        for (int ks = 0; ks < 2; ks++) {
            const int k8 = ks * 8;
            unsigned a[2][4];
            #pragma unroll
            for (int mi = 0; mi < 2; mi++) {
                int r = wm * 32 + mi * 16 + g;
                a[mi][0] = __float_as_uint(As[r][k8 + t]);
                a[mi][1] = __float_as_uint(As[r + 8][k8 + t]);
                a[mi][2] = __float_as_uint(As[r][k8 + t + 4]);
                a[mi][3] = __float_as_uint(As[r + 8][k8 + t + 4]);
            }
            #pragma unroll
            for (int f = 0; f < 8; f++) {
                unsigned b[2];
                const int nc = wn * 64 + f * 8 + g;
                b[0] = __float_as_uint(Bs[k8 + t][nc]);
                b[1] = __float_as_uint(Bs[k8 + t + 4][nc]);
                mma8(c[0][f], a[0], b);
                mma8(c[1][f], a[1], b);
            }
        }
        __syncthreads();
    }

    #pragma unroll
    for (int mi = 0; mi < 2; mi++) {
        const int r0 = m0 + wm * 32 + mi * 16 + g;
        #pragma unroll
        for (int f = 0; f < 8; f++) {
            const int col = n0 + wn * 64 + f * 8 + t * 2;
            const float b0v = bo[col], b1v = bo[col + 1];
            float2 v0; v0.x = c[mi][f][0] + b0v; v0.y = c[mi][f][1] + b1v;
            *(float2*)(out + (size_t)r0 * E_ + col) = v0;
            float2 v1; v1.x = c[mi][f][2] + b0v; v1.y = c[mi][f][3] + b1v;
            *(float2*)(out + (size_t)(r0 + 8) * E_ + col) = v1;
        }
    }
}

// ---------------------------------------------------------------------------
extern "C" void kernel_launch(void* const* d_in, const int* in_sizes, int n_in,
                              void* d_out, int out_size)
{
    const float* x  = (const float*)d_in[0];
    const float* Wq = (const float*)d_in[1];
    const float* Wk = (const float*)d_in[2];
    const float* Wv = (const float*)d_in[3];
    const float* bq = (const float*)d_in[4];
    const float* bk = (const float*)d_in[5];
    const float* bv = (const float*)d_in[6];
    const float* Wo = (const float*)d_in[7];
    const float* bo = (const float*)d_in[8];
    float* out = (float*)d_out;

    cudaFuncSetAttribute(flash_kernel,
                         cudaFuncAttributeMaxDynamicSharedMemorySize, FLASH_SMEM);

    qkv_kernel<<<dim3(BS_ / 256, 24), 512>>>(x, Wq, Wk, Wv, bq, bk, bv);
    flash_kernel<<<dim3(S_ / 128, H_, B_), 256, FLASH_SMEM>>>();
    oproj_kernel<<<dim3(BS_ / 256, E_ / 128), 512>>>(Wo, bo, out);
}

// round 3
// speedup vs baseline: 3.4292x; 1.4582x over previous
#include <cuda_runtime.h>
#include <cstdint>

#define B_ 4
#define S_ 2048
#define E_ 1024
#define H_ 16
#define D_ 64
#define BS_ (B_*S_)
#define BHSD (B_*H_*S_*D_)

// Scratch (device globals — no allocations allowed)
__device__ __align__(16) float g_buf[3*(size_t)BHSD]; // Q|K|V rounded (Q pre-scaled)
__device__ __align__(16) float g_ctx[(size_t)BS_*H_*D_];
__device__ __align__(16) float g_xr[(size_t)BS_*E_];
__device__ __align__(16) float g_Wqr[H_*E_*D_];
__device__ __align__(16) float g_Wkr[H_*E_*D_];
__device__ __align__(16) float g_Wvr[H_*E_*D_];
__device__ __align__(16) float g_Wor[H_*D_*E_];

// ---------------------------------------------------------------------------
__device__ __forceinline__ float f2tff(float f) {
    unsigned u; asm("cvt.rna.tf32.f32 %0, %1;" : "=r"(u) : "f"(f));
    return __uint_as_float(u);
}
__device__ __forceinline__ void mma8(float* c, const unsigned* a, const unsigned* b) {
    asm volatile(
        "mma.sync.aligned.m16n8k8.row.col.f32.tf32.tf32.f32 "
        "{%0,%1,%2,%3}, {%4,%5,%6,%7}, {%8,%9}, {%0,%1,%2,%3};\n"
        : "+f"(c[0]), "+f"(c[1]), "+f"(c[2]), "+f"(c[3])
        : "r"(a[0]), "r"(a[1]), "r"(a[2]), "r"(a[3]), "r"(b[0]), "r"(b[1]));
}
__device__ __forceinline__ void cp16(uint32_t d, const float* s) {
    asm volatile("cp.async.cg.shared.global [%0], [%1], 16;\n" :: "r"(d), "l"(s));
}
__device__ __forceinline__ void cp_commit() { asm volatile("cp.async.commit_group;\n"); }
__device__ __forceinline__ void cp_wait0()  { asm volatile("cp.async.wait_group 0;\n" ::: "memory"); }

// ---------------------------------------------------------------------------
// prep: round a float array to tf32 (rna) into one of the device scratch arrays
// ---------------------------------------------------------------------------
__global__ void prep_kernel(const float4* __restrict__ src, int which, int n4)
{
    float4* dst = (which == 0) ? (float4*)g_xr  :
                  (which == 1) ? (float4*)g_Wqr :
                  (which == 2) ? (float4*)g_Wkr :
                  (which == 3) ? (float4*)g_Wvr : (float4*)g_Wor;
    int i = blockIdx.x * blockDim.x + threadIdx.x;
    int stride = gridDim.x * blockDim.x;
    for (; i < n4; i += stride) {
        float4 v = src[i];
        float4 w;
        w.x = f2tff(v.x); w.y = f2tff(v.y); w.z = f2tff(v.z); w.w = f2tff(v.w);
        dst[i] = w;
    }
}

// ---------------------------------------------------------------------------
// Kernel 1: fused QKV projection, tf32 mma, cp.async double-buffered.
// Block tile 128(M) x 128(N = two (w,h) outputs), K-tile 32, 256 thr / 8 warps
// (wm 0..3, wn 0..1; warp tile 32x64). grid (64, 24).
// smem: As[2][128][36] + Bs[2][32][136] = 71680 B (dynamic).
// ---------------------------------------------------------------------------
#define GEMM_SMEM 71680

__global__ __launch_bounds__(256, 2) void qkv_kernel(
    const float* __restrict__ bq, const float* __restrict__ bk, const float* __restrict__ bv)
{
    extern __shared__ float sm[];
    const int tid  = threadIdx.x;
    const int m0   = blockIdx.x * 128;
    const int p0   = blockIdx.y * 2;
    const int lane = tid & 31, wid = tid >> 5;
    const int wm   = wid >> 1, wn = wid & 1;
    const int g    = lane >> 2, t = lane & 3;
    const uint32_t smb = (uint32_t)__cvta_generic_to_shared(sm);

    const float* aSrc[4]; uint32_t aDst[4];
    #pragma unroll
    for (int i = 0; i < 4; i++) {
        int lin = tid + i * 256, row = lin >> 3, c4 = lin & 7;
        aSrc[i] = g_xr + (size_t)(m0 + row) * E_ + c4 * 4;
        aDst[i] = smb + (uint32_t)(row * 36 + c4 * 4) * 4u;
    }
    const float* bSrc[4]; uint32_t bDst[4];
    #pragma unroll
    for (int i = 0; i < 4; i++) {
        int lin = tid + i * 256, row = lin >> 5, c4 = lin & 31, ncol = c4 * 4;
        int pb = p0 + (c4 >> 4), wv = pb >> 4, hh = pb & 15;
        const float* base = (wv == 0) ? g_Wqr : (wv == 1) ? g_Wkr : g_Wvr;
        bSrc[i] = base + (size_t)hh * E_ * D_ + row * D_ + (ncol & 63);
        bDst[i] = smb + (uint32_t)(9216 + row * 136 + ncol) * 4u;
    }

    // prefetch tile 0 -> stage 0
    #pragma unroll
    for (int i = 0; i < 4; i++) { cp16(aDst[i], aSrc[i]); cp16(bDst[i], bSrc[i]); }
    cp_commit();

    float c[2][8][4];
    #pragma unroll
    for (int mi = 0; mi < 2; mi++)
        #pragma unroll
        for (int f = 0; f < 8; f++)
            #pragma unroll
            for (int r = 0; r < 4; r++) c[mi][f][r] = 0.f;

    for (int kt = 0; kt < 32; kt++) {
        cp_wait0();
        __syncthreads();
        if (kt + 1 < 32) {
            const uint32_t st = ((kt + 1) & 1);
            #pragma unroll
            for (int i = 0; i < 4; i++) {
                cp16(aDst[i] + st * 18432u, aSrc[i] + (size_t)(kt + 1) * 32);
                cp16(bDst[i] + st * 17408u, bSrc[i] + (size_t)(kt + 1) * 32 * D_);
            }
            cp_commit();
        }
        const float* A  = sm + (kt & 1) * 4608;
        const float* Bt = sm + 9216 + (kt & 1) * 4352;

        #pragma unroll
        for (int ks = 0; ks < 4; ks++) {
            const int k8 = ks * 8;
            unsigned a[2][4];
            #pragma unroll
            for (int mi = 0; mi < 2; mi++) {
                int r = wm * 32 + mi * 16 + g;
                a[mi][0] = __float_as_uint(A[r * 36 + k8 + t]);
                a[mi][1] = __float_as_uint(A[(r + 8) * 36 + k8 + t]);
                a[mi][2] = __float_as_uint(A[r * 36 + k8 + t + 4]);
                a[mi][3] = __float_as_uint(A[(r + 8) * 36 + k8 + t + 4]);
            }
            #pragma unroll
            for (int f = 0; f < 8; f++) {
                unsigned b[2];
                const int nc = wn * 64 + f * 8 + g;
                b[0] = __float_as_uint(Bt[(k8 + t) * 136 + nc]);
                b[1] = __float_as_uint(Bt[(k8 + t + 4) * 136 + nc]);
                mma8(c[0][f], a[0], b);
                mma8(c[1][f], a[1], b);
            }
        }
    }

    // epilogue: bias + tf32-round (+0.125 scale for Q) -> g_buf [B,H,S,D]
    const int p  = p0 + wn;
    const int wv = p >> 4, hh = p & 15;
    float* outb = g_buf + (size_t)wv * BHSD;
    const float* bb = ((wv == 0) ? bq : (wv == 1) ? bk : bv) + hh * D_;
    const float scl = (wv == 0) ? 0.125f : 1.0f;

    #pragma unroll
    for (int mi = 0; mi < 2; mi++) {
        const int r0 = m0 + wm * 32 + mi * 16 + g;
        #pragma unroll
        for (int f = 0; f < 8; f++) {
            const int col = f * 8 + t * 2;
            const float b0v = bb[col], b1v = bb[col + 1];
            {
                int gr = r0;
                float2 v;
                v.x = f2tff((c[mi][f][0] + b0v) * scl);
                v.y = f2tff((c[mi][f][1] + b1v) * scl);
                *(float2*)(outb + (((size_t)(gr >> 11) * H_ + hh) * S_ + (gr & 2047)) * D_ + col) = v;
            }
            {
                int gr = r0 + 8;
                float2 v;
                v.x = f2tff((c[mi][f][2] + b0v) * scl);
                v.y = f2tff((c[mi][f][3] + b1v) * scl);
                *(float2*)(outb + (((size_t)(gr >> 11) * H_ + hh) * S_ + (gr & 2047)) * D_ + col) = v;
            }
        }
    }
}

// ---------------------------------------------------------------------------
// Kernel 2: causal flash attention, tf32 mma, cp.async K/V double buffer.
// Block = 128 queries of one (b,h), Bkv=64, 256 thr / 8 warps; Q frags in regs.
// smem: Ks[2][64][68] + Vs[2][64][72] + Ps[128][68] = 106496 B.
// ---------------------------------------------------------------------------
#define FLASH_SMEM 106496

__global__ __launch_bounds__(256, 2) void flash_kernel()
{
    extern __shared__ float sm[];
    float* Ps = sm + 17920;

    const int iq = blockIdx.x, h = blockIdx.y, b = blockIdx.z;
    const int q0 = iq * 128;
    const size_t head_base = ((size_t)b * H_ + h) * S_ * D_;
    const float* Qg = g_buf + head_base;          // pre-scaled, rounded
    const float* Kg = g_buf + BHSD + head_base;   // rounded

    const int tid  = threadIdx.x;
    const int lane = tid & 31, wid = tid >> 5;
    const int g    = lane >> 2, t = lane & 3;
    const int qrow = wid * 16 + g;
    const uint32_t smb = (uint32_t)__cvta_generic_to_shared(sm);

    const float* kSrc[4]; uint32_t kDst[4], vDst[4];
    #pragma unroll
    for (int i = 0; i < 4; i++) {
        int lin = tid + i * 256, row = lin >> 4, c4 = lin & 15;
        kSrc[i] = Kg + (size_t)row * D_ + c4 * 4;
        kDst[i] = smb + (uint32_t)(row * 68 + c4 * 4) * 4u;
        vDst[i] = smb + (uint32_t)(8704 + row * 72 + c4 * 4) * 4u;
    }

    // prefetch K/V tile 0 -> stage 0
    #pragma unroll
    for (int i = 0; i < 4; i++) { cp16(kDst[i], kSrc[i]); cp16(vDst[i], kSrc[i] + BHSD); }
    cp_commit();

    // stage Q into Ps (one-time), then lift warp-private A-fragments to regs
    #pragma unroll
    for (int i = 0; i < 8; i++) {
        int lin = tid + i * 256, row = lin >> 4, c4 = lin & 15;
        *(float4*)&Ps[row * 68 + c4 * 4] =
            *(const float4*)(Qg + (size_t)(q0 + row) * D_ + c4 * 4);
    }
    __syncthreads();

    unsigned aQ[8][4];
    #pragma unroll
    for (int kk = 0; kk < 8; kk++) {
        const int d8 = kk * 8;
        aQ[kk][0] = __float_as_uint(Ps[qrow * 68 + d8 + t]);
        aQ[kk][1] = __float_as_uint(Ps[(qrow + 8) * 68 + d8 + t]);
        aQ[kk][2] = __float_as_uint(Ps[qrow * 68 + d8 + t + 4]);
        aQ[kk][3] = __float_as_uint(Ps[(qrow + 8) * 68 + d8 + t + 4]);
    }

    float cO[8][4];
    #pragma unroll
    for (int f = 0; f < 8; f++)
        #pragma unroll
        for (int r = 0; r < 4; r++) cO[f][r] = 0.f;
    float m0_ = -1e30f, m1_ = -1e30f, l0_ = 0.f, l1_ = 0.f;

    const int jtmax = 2 * iq + 1;
    for (int jt = 0; jt <= jtmax; jt++) {
        cp_wait0();
        __syncthreads();
        if (jt < jtmax) {
            const uint32_t st = ((jt + 1) & 1);
            #pragma unroll
            for (int i = 0; i < 4; i++) {
                cp16(kDst[i] + st * 17408u, kSrc[i] + (size_t)(jt + 1) * 4096);
                cp16(vDst[i] + st * 18432u, kSrc[i] + BHSD + (size_t)(jt + 1) * 4096);
            }
            cp_commit();
        }
        const float* Kst = sm + (jt & 1) * 4352;
        const float* Vst = sm + 8704 + (jt & 1) * 4608;
        const int k0 = jt * 64;

        // S = Q K^T
        float cS[8][4];
        #pragma unroll
        for (int f = 0; f < 8; f++)
            #pragma unroll
            for (int r = 0; r < 4; r++) cS[f][r] = 0.f;

        #pragma unroll
        for (int kk = 0; kk < 8; kk++) {
            const int d8 = kk * 8;
            #pragma unroll
            for (int f = 0; f < 8; f++) {
                unsigned bfr[2];
                bfr[0] = __float_as_uint(Kst[(f * 8 + g) * 68 + d8 + t]);
                bfr[1] = __float_as_uint(Kst[(f * 8 + g) * 68 + d8 + t + 4]);
                mma8(cS[f], aQ[kk], bfr);
            }
        }

        if (jt >= 2 * iq) {
            const int r0 = q0 + qrow, r1 = r0 + 8;
            #pragma unroll
            for (int f = 0; f < 8; f++) {
                const int col = k0 + f * 8 + t * 2;
                if (col     > r0) cS[f][0] = -1e30f;
                if (col + 1 > r0) cS[f][1] = -1e30f;
                if (col     > r1) cS[f][2] = -1e30f;
                if (col + 1 > r1) cS[f][3] = -1e30f;
            }
        }

        // online softmax
        float rm0 = -1e30f, rm1 = -1e30f;
        #pragma unroll
        for (int f = 0; f < 8; f++) {
            rm0 = fmaxf(rm0, fmaxf(cS[f][0], cS[f][1]));
            rm1 = fmaxf(rm1, fmaxf(cS[f][2], cS[f][3]));
        }
        rm0 = fmaxf(rm0, __shfl_xor_sync(0xffffffffu, rm0, 1));
        rm0 = fmaxf(rm0, __shfl_xor_sync(0xffffffffu, rm0, 2));
        rm1 = fmaxf(rm1, __shfl_xor_sync(0xffffffffu, rm1, 1));
        rm1 = fmaxf(rm1, __shfl_xor_sync(0xffffffffu, rm1, 2));

        const float nm0 = fmaxf(m0_, rm0);
        const float nm1 = fmaxf(m1_, rm1);
        const float corr0 = __expf(m0_ - nm0);
        const float corr1 = __expf(m1_ - nm1);
        m0_ = nm0; m1_ = nm1;

        float rs0 = 0.f, rs1 = 0.f;
        #pragma unroll
        for (int f = 0; f < 8; f++) {
            float p0v = __expf(cS[f][0] - nm0);
            float p1v = __expf(cS[f][1] - nm0);
            float p2v = __expf(cS[f][2] - nm1);
            float p3v = __expf(cS[f][3] - nm1);
            rs0 += p0v + p1v;
            rs1 += p2v + p3v;
            float2 v0; v0.x = f2tff(p0v); v0.y = f2tff(p1v);
            *(float2*)&Ps[qrow * 68 + f * 8 + t * 2] = v0;
            float2 v1; v1.x = f2tff(p2v); v1.y = f2tff(p3v);
            *(float2*)&Ps[(qrow + 8) * 68 + f * 8 + t * 2] = v1;
        }
        rs0 += __shfl_xor_sync(0xffffffffu, rs0, 1);
        rs0 += __shfl_xor_sync(0xffffffffu, rs0, 2);
        rs1 += __shfl_xor_sync(0xffffffffu, rs1, 1);
        rs1 += __shfl_xor_sync(0xffffffffu, rs1, 2);
        l0_ = l0_ * corr0 + rs0;
        l1_ = l1_ * corr1 + rs1;
        #pragma unroll
        for (int f = 0; f < 8; f++) {
            cO[f][0] *= corr0; cO[f][1] *= corr0;
            cO[f][2] *= corr1; cO[f][3] *= corr1;
        }
        __syncwarp();

        // O += P V
        #pragma unroll
        for (int kk = 0; kk < 8; kk++) {
            const int s8 = kk * 8;
            unsigned a[4];
            a[0] = __float_as_uint(Ps[qrow * 68 + s8 + t]);
            a[1] = __float_as_uint(Ps[(qrow + 8) * 68 + s8 + t]);
            a[2] = __float_as_uint(Ps[qrow * 68 + s8 + t + 4]);
            a[3] = __float_as_uint(Ps[(qrow + 8) * 68 + s8 + t + 4]);
            #pragma unroll
            for (int f = 0; f < 8; f++) {
                unsigned bfr[2];
                bfr[0] = __float_as_uint(Vst[(s8 + t) * 72 + f * 8 + g]);
                bfr[1] = __float_as_uint(Vst[(s8 + t + 4) * 72 + f * 8 + g]);
                mma8(cO[f], a, bfr);
            }
        }
    }

    // epilogue: normalize, round (oproj A operand), write ctx [B,S,H,D]
    const float inv0 = 1.0f / l0_;
    const float inv1 = 1.0f / l1_;
    const int q_a = q0 + qrow, q_b = q_a + 8;
    #pragma unroll
    for (int f = 0; f < 8; f++) {
        const int col = f * 8 + t * 2;
        float2 v0; v0.x = f2tff(cO[f][0] * inv0); v0.y = f2tff(cO[f][1] * inv0);
        *(float2*)(g_ctx + (((size_t)b * S_ + q_a) * H_ + h) * D_ + col) = v0;
        float2 v1; v1.x = f2tff(cO[f][2] * inv1); v1.y = f2tff(cO[f][3] * inv1);
        *(float2*)(g_ctx + (((size_t)b * S_ + q_b) * H_ + h) * D_ + col) = v1;
    }
}

// ---------------------------------------------------------------------------
// Kernel 3: output projection, same skeleton as qkv. grid (64, 8).
// ---------------------------------------------------------------------------
__global__ __launch_bounds__(256, 2) void oproj_kernel(
    const float* __restrict__ bo, float* __restrict__ out)
{
    extern __shared__ float sm[];
    const int tid  = threadIdx.x;
    const int m0   = blockIdx.x * 128;
    const int n0   = blockIdx.y * 128;
    const int lane = tid & 31, wid = tid >> 5;
    const int wm   = wid >> 1, wn = wid & 1;
    const int g    = lane >> 2, t = lane & 3;
    const uint32_t smb = (uint32_t)__cvta_generic_to_shared(sm);

    const float* aSrc[4]; uint32_t aDst[4];
    #pragma unroll
    for (int i = 0; i < 4; i++) {
        int lin = tid + i * 256, row = lin >> 3, c4 = lin & 7;
        aSrc[i] = g_ctx + (size_t)(m0 + row) * E_ + c4 * 4;
        aDst[i] = smb + (uint32_t)(row * 36 + c4 * 4) * 4u;
    }
    const float* bSrc[4]; uint32_t bDst[4];
    #pragma unroll
    for (int i = 0; i < 4; i++) {
        int lin = tid + i * 256, row = lin >> 5, c4 = lin & 31, ncol = c4 * 4;
        bSrc[i] = g_Wor + (size_t)row * E_ + n0 + ncol;
        bDst[i] = smb + (uint32_t)(9216 + row * 136 + ncol) * 4u;
    }

    #pragma unroll
    for (int i = 0; i < 4; i++) { cp16(aDst[i], aSrc[i]); cp16(bDst[i], bSrc[i]); }
    cp_commit();

    float c[2][8][4];
    #pragma unroll
    for (int mi = 0; mi < 2; mi++)
        #pragma unroll
        for (int f = 0; f < 8; f++)
            #pragma unroll
            for (int r = 0; r < 4; r++) c[mi][f][r] = 0.f;

    for (int kt = 0; kt < 32; kt++) {
        cp_wait0();
        __syncthreads();
        if (kt + 1 < 32) {
            const uint32_t st = ((kt + 1) & 1);
            #pragma unroll
            for (int i = 0; i < 4; i++) {
                cp16(aDst[i] + st * 18432u, aSrc[i] + (size_t)(kt + 1) * 32);
                cp16(bDst[i] + st * 17408u, bSrc[i] + (size_t)(kt + 1) * 32 * E_);
            }
            cp_commit();
        }
        const float* A  = sm + (kt & 1) * 4608;
        const float* Bt = sm + 9216 + (kt & 1) * 4352;

        #pragma unroll
        for (int ks = 0; ks < 4; ks++) {
            const int k8 = ks * 8;
            unsigned a[2][4];
            #pragma unroll
            for (int mi = 0; mi < 2; mi++) {
                int r = wm * 32 + mi * 16 + g;
                a[mi][0] = __float_as_uint(A[r * 36 + k8 + t]);
                a[mi][1] = __float_as_uint(A[(r + 8) * 36 + k8 + t]);
                a[mi][2] = __float_as_uint(A[r * 36 + k8 + t + 4]);
                a[mi][3] = __float_as_uint(A[(r + 8) * 36 + k8 + t + 4]);
            }
            #pragma unroll
            for (int f = 0; f < 8; f++) {
                unsigned b[2];
                const int nc = wn * 64 + f * 8 + g;
                b[0] = __float_as_uint(Bt[(k8 + t) * 136 + nc]);
                b[1] = __float_as_uint(Bt[(k8 + t + 4) * 136 + nc]);
                mma8(c[0][f], a[0], b);
                mma8(c[1][f], a[1], b);
            }
        }
    }

    #pragma unroll
    for (int mi = 0; mi < 2; mi++) {
        const int r0 = m0 + wm * 32 + mi * 16 + g;
        #pragma unroll
        for (int f = 0; f < 8; f++) {
            const int col = n0 + wn * 64 + f * 8 + t * 2;
            const float b0v = bo[col], b1v = bo[col + 1];
            float2 v0; v0.x = c[mi][f][0] + b0v; v0.y = c[mi][f][1] + b1v;
            *(float2*)(out + (size_t)r0 * E_ + col) = v0;
            float2 v1; v1.x = c[mi][f][2] + b0v; v1.y = c[mi][f][3] + b1v;
            *(float2*)(out + (size_t)(r0 + 8) * E_ + col) = v1;
        }
    }
}

// ---------------------------------------------------------------------------
extern "C" void kernel_launch(void* const* d_in, const int* in_sizes, int n_in,
                              void* d_out, int out_size)
{
    const float* x  = (const float*)d_in[0];
    const float* Wq = (const float*)d_in[1];
    const float* Wk = (const float*)d_in[2];
    const float* Wv = (const float*)d_in[3];
    const float* bq = (const float*)d_in[4];
    const float* bk = (const float*)d_in[5];
    const float* bv = (const float*)d_in[6];
    const float* Wo = (const float*)d_in[7];
    const float* bo = (const float*)d_in[8];
    float* out = (float*)d_out;

    cudaFuncSetAttribute(qkv_kernel,  cudaFuncAttributeMaxDynamicSharedMemorySize, GEMM_SMEM);
    cudaFuncSetAttribute(flash_kernel, cudaFuncAttributeMaxDynamicSharedMemorySize, FLASH_SMEM);
    cudaFuncSetAttribute(oproj_kernel, cudaFuncAttributeMaxDynamicSharedMemorySize, GEMM_SMEM);

    prep_kernel<<<2048, 256>>>((const float4*)x,  0, BS_ * E_ / 4);
    prep_kernel<<<512,  256>>>((const float4*)Wq, 1, H_ * E_ * D_ / 4);
    prep_kernel<<<512,  256>>>((const float4*)Wk, 2, H_ * E_ * D_ / 4);
    prep_kernel<<<512,  256>>>((const float4*)Wv, 3, H_ * E_ * D_ / 4);
    prep_kernel<<<512,  256>>>((const float4*)Wo, 4, H_ * D_ * E_ / 4);

    qkv_kernel<<<dim3(BS_ / 128, 24), 256, GEMM_SMEM>>>(bq, bk, bv);
    flash_kernel<<<dim3(S_ / 128, H_, B_), 256, FLASH_SMEM>>>();
    oproj_kernel<<<dim3(BS_ / 128, E_ / 128), 256, GEMM_SMEM>>>(bo, out);
}